// round 1
// baseline (speedup 1.0000x reference)
#include <cuda_runtime.h>
#include <cstdint>

// Problem constants (structural): B=2, D=64. N and E read from in_sizes.
#define BB 2
#define DD 64
#define MAXN 50000

// Scratch (static __device__ — no allocations allowed).
// g_P   : prev @ W^T  (pre-transformed embeddings)
// g_nbr : scatter accumulator (already in transformed space)
__device__ float g_P  [(size_t)BB * MAXN * DD];
__device__ float g_nbr[(size_t)BB * MAXN * DD];

// ---------------------------------------------------------------------------
// Kernel 1: P[row] = prev[row] @ W^T ; also zero g_nbr[row].
// One thread per (b,n) row. W cached in shared memory (16 KB), broadcast LDS.
// ---------------------------------------------------------------------------
__global__ __launch_bounds__(128)
void k_transform(const float* __restrict__ prev, const float* __restrict__ W,
                 int nRows)
{
    __shared__ float Ws[DD * DD];
    for (int i = threadIdx.x; i < DD * DD; i += blockDim.x) Ws[i] = W[i];
    __syncthreads();

    int row = blockIdx.x * blockDim.x + threadIdx.x;
    if (row >= nRows) return;

    const float4* pr = reinterpret_cast<const float4*>(prev) + (size_t)row * 16;
    float4 r[16];
#pragma unroll
    for (int k = 0; k < 16; k++) r[k] = pr[k];

    float4* oP = reinterpret_cast<float4*>(g_P)   + (size_t)row * 16;
    float4* oN = reinterpret_cast<float4*>(g_nbr) + (size_t)row * 16;
    const float4* W4 = reinterpret_cast<const float4*>(Ws);

    // Keep outer loop rolled: body ~5KB fits I$; inner fully unrolled.
#pragma unroll 1
    for (int e4 = 0; e4 < 16; e4++) {
        float ax = 0.f, ay = 0.f, az = 0.f, aw = 0.f;
#pragma unroll
        for (int k = 0; k < 16; k++) {
            float4 rk = r[k];
            float4 w0 = W4[(e4 * 4 + 0) * 16 + k];
            float4 w1 = W4[(e4 * 4 + 1) * 16 + k];
            float4 w2 = W4[(e4 * 4 + 2) * 16 + k];
            float4 w3 = W4[(e4 * 4 + 3) * 16 + k];
            ax += rk.x * w0.x + rk.y * w0.y + rk.z * w0.z + rk.w * w0.w;
            ay += rk.x * w1.x + rk.y * w1.y + rk.z * w1.z + rk.w * w1.w;
            az += rk.x * w2.x + rk.y * w2.y + rk.z * w2.z + rk.w * w2.w;
            aw += rk.x * w3.x + rk.y * w3.y + rk.z * w3.z + rk.w * w3.w;
        }
        oP[e4] = make_float4(ax, ay, az, aw);
        oN[e4] = make_float4(0.f, 0.f, 0.f, 0.f);
    }
}

// ---------------------------------------------------------------------------
// Kernel 2: edge scatter (both directions, both batches) via vector RED.
// One warp per edge: lanes 0-15 = batch 0 (float4 chunk k=lane),
//                    lanes 16-31 = batch 1.
// g_nbr[b][v] += P[b][u] * g ;  g_nbr[b][u] += P[b][v] * g
// ---------------------------------------------------------------------------
__device__ __forceinline__ void red_add_v4(float* addr, float x, float y,
                                           float z, float w)
{
    asm volatile("red.global.add.v4.f32 [%0], {%1, %2, %3, %4};"
                 :: "l"(addr), "f"(x), "f"(y), "f"(z), "f"(w)
                 : "memory");
}

__global__ __launch_bounds__(256)
void k_scatter(const int* __restrict__ edges, const float* __restrict__ status,
               int N, int E)
{
    int gw = (blockIdx.x * blockDim.x + threadIdx.x) >> 5;
    if (gw >= E) return;
    int lane = threadIdx.x & 31;

    // All lanes load the same 3 words -> single sectors, L1-friendly.
    int   u = __ldg(edges + 2 * (size_t)gw);
    int   v = __ldg(edges + 2 * (size_t)gw + 1);
    float g = __ldg(status + gw);

    int b = lane >> 4;        // batch
    int k = lane & 15;        // float4 chunk within the 64-float row

    size_t iu = ((size_t)b * N + u) * 16 + k;   // float4 index
    size_t iv = ((size_t)b * N + v) * 16 + k;

    const float4* P4 = reinterpret_cast<const float4*>(g_P);
    float4 pu = __ldg(P4 + iu);
    float4 pv = __ldg(P4 + iv);

    float* nu = g_nbr + iu * 4;
    float* nv = g_nbr + iv * 4;

    red_add_v4(nv, pu.x * g, pu.y * g, pu.z * g, pu.w * g);
    red_add_v4(nu, pv.x * g, pv.y * g, pv.z * g, pv.w * g);
}

// ---------------------------------------------------------------------------
// Kernel 3: out = leaky_relu(node + edge + nbr), slope 0.01. float4 streaming.
// ---------------------------------------------------------------------------
__global__ __launch_bounds__(256)
void k_final(const float* __restrict__ nodef, const float* __restrict__ edgef,
             float* __restrict__ out, int total4)
{
    int i = blockIdx.x * blockDim.x + threadIdx.x;
    if (i >= total4) return;

    float4 a = reinterpret_cast<const float4*>(nodef)[i];
    float4 b = reinterpret_cast<const float4*>(edgef)[i];
    float4 c = reinterpret_cast<const float4*>(g_nbr)[i];

    float4 s;
    s.x = a.x + b.x + c.x;
    s.y = a.y + b.y + c.y;
    s.z = a.z + b.z + c.z;
    s.w = a.w + b.w + c.w;
    s.x = (s.x >= 0.f) ? s.x : 0.01f * s.x;
    s.y = (s.y >= 0.f) ? s.y : 0.01f * s.y;
    s.z = (s.z >= 0.f) ? s.z : 0.01f * s.z;
    s.w = (s.w >= 0.f) ? s.w : 0.01f * s.w;

    reinterpret_cast<float4*>(out)[i] = s;
}

// ---------------------------------------------------------------------------
// Launch
// ---------------------------------------------------------------------------
extern "C" void kernel_launch(void* const* d_in, const int* in_sizes, int n_in,
                              void* d_out, int out_size)
{
    const float* prev  = (const float*)d_in[0];
    const int*   edges = (const int*)  d_in[1];
    const float* nodef = (const float*)d_in[2];
    const float* edgef = (const float*)d_in[3];
    const float* stat  = (const float*)d_in[4];
    const float* W     = (const float*)d_in[5];
    float* out = (float*)d_out;

    int E     = in_sizes[4];
    int nRows = in_sizes[0] / DD;   // B*N
    int N     = nRows / BB;

    k_transform<<<(nRows + 127) / 128, 128>>>(prev, W, nRows);

    long long threads = (long long)E * 32;
    k_scatter<<<(unsigned)((threads + 255) / 256), 256>>>(edges, stat, N, E);

    int total4 = nRows * 16;
    k_final<<<(total4 + 255) / 256, 256>>>(nodef, edgef, out, total4);
}